// round 3
// baseline (speedup 1.0000x reference)
#include <cuda_runtime.h>
#include <cstdint>

#define BATCH 4
#define SEQ   2048
#define NH    16
#define DH    64
#define DM    1024
#define MROWS (BATCH*SEQ)   // 8192

// Scratch (static device globals; no runtime allocation)
__device__ float g_q[(size_t)BATCH*NH*SEQ*DH];
__device__ float g_k[(size_t)BATCH*NH*SEQ*DH];
__device__ float g_v[(size_t)BATCH*NH*SEQ*DH];
__device__ float g_o[(size_t)MROWS*DM];

__device__ __forceinline__ uint32_t f2tf(float x) {
    uint32_t u;
    asm("cvt.rna.tf32.f32 %0, %1;" : "=r"(u) : "f"(x));
    return u;
}
__device__ __forceinline__ float f2tff(float x) { return __uint_as_float(f2tf(x)); }

__device__ __forceinline__ void mma_tf32(float* c,
    uint32_t a0, uint32_t a1, uint32_t a2, uint32_t a3,
    uint32_t b0, uint32_t b1)
{
    asm volatile(
        "mma.sync.aligned.m16n8k8.row.col.f32.tf32.tf32.f32 "
        "{%0,%1,%2,%3}, {%4,%5,%6,%7}, {%8,%9}, {%0,%1,%2,%3};"
        : "+f"(c[0]), "+f"(c[1]), "+f"(c[2]), "+f"(c[3])
        : "r"(a0), "r"(a1), "r"(a2), "r"(a3), "r"(b0), "r"(b1));
}

// ---------------------------------------------------------------------------
// QKV projection: tf32 tensor-core GEMM, 128x64 tile per block.
// out[b,h,p,d] = sum_m x[b,p,m] * W[h,m,d] + bias[h,d]
// ---------------------------------------------------------------------------
__global__ __launch_bounds__(256) void qkv_kernel(
    const float* __restrict__ X,
    const float* __restrict__ Qw, const float* __restrict__ Qb,
    const float* __restrict__ Kw, const float* __restrict__ Kb,
    const float* __restrict__ Vw, const float* __restrict__ Vb)
{
    const int m0    = blockIdx.x * 128;
    const int h     = blockIdx.y;
    const int which = blockIdx.z;

    const float* W    = (which == 0 ? Qw : which == 1 ? Kw : Vw) + (size_t)h * DM * DH;
    const float* bias = (which == 0 ? Qb : which == 1 ? Kb : Vb) + h * DH;
    float* Out        = (which == 0 ? g_q : which == 1 ? g_k : g_v);

    __shared__ float As[128][36];   // [m][k], BK=32, pad->banks (4g+t) distinct
    __shared__ float Bs[32][72];    // [k][n], pad->banks (8t+g) distinct

    const int tid  = threadIdx.x;
    const int lane = tid & 31;
    const int w    = tid >> 5;
    const int wm   = w >> 1;     // 0..3
    const int wn   = w & 1;      // 0..1
    const int g    = lane >> 2;  // 0..7
    const int t    = lane & 3;   // 0..3

    float c[2][4][4];
#pragma unroll
    for (int mt = 0; mt < 2; mt++)
#pragma unroll
        for (int nt = 0; nt < 4; nt++)
#pragma unroll
            for (int i = 0; i < 4; i++) c[mt][nt][i] = 0.f;

    for (int k0 = 0; k0 < DM; k0 += 32) {
#pragma unroll
        for (int i = 0; i < 4; i++) {
            int lin = tid + i * 256;       // float4 id, 1024 total
            int row = lin >> 3;
            int c4  = lin & 7;
            float4 v = *(const float4*)&X[(size_t)(m0 + row) * DM + k0 + c4 * 4];
            As[row][c4 * 4 + 0] = f2tff(v.x);
            As[row][c4 * 4 + 1] = f2tff(v.y);
            As[row][c4 * 4 + 2] = f2tff(v.z);
            As[row][c4 * 4 + 3] = f2tff(v.w);
        }
#pragma unroll
        for (int i = 0; i < 2; i++) {
            int lin = tid + i * 256;       // 512 float4 total
            int row = lin >> 4;
            int c4  = lin & 15;
            float4 v = *(const float4*)&W[(size_t)(k0 + row) * DH + c4 * 4];
            Bs[row][c4 * 4 + 0] = f2tff(v.x);
            Bs[row][c4 * 4 + 1] = f2tff(v.y);
            Bs[row][c4 * 4 + 2] = f2tff(v.z);
            Bs[row][c4 * 4 + 3] = f2tff(v.w);
        }
        __syncthreads();

#pragma unroll
        for (int ks = 0; ks < 4; ks++) {
            uint32_t a[2][4], bb[4][2];
#pragma unroll
            for (int mt = 0; mt < 2; mt++) {
                int r0 = wm * 32 + mt * 16 + g;
                a[mt][0] = __float_as_uint(As[r0][ks * 8 + t]);
                a[mt][1] = __float_as_uint(As[r0 + 8][ks * 8 + t]);
                a[mt][2] = __float_as_uint(As[r0][ks * 8 + t + 4]);
                a[mt][3] = __float_as_uint(As[r0 + 8][ks * 8 + t + 4]);
            }
#pragma unroll
            for (int nt = 0; nt < 4; nt++) {
                int col = wn * 32 + nt * 8 + g;
                bb[nt][0] = __float_as_uint(Bs[ks * 8 + t][col]);
                bb[nt][1] = __float_as_uint(Bs[ks * 8 + t + 4][col]);
            }
#pragma unroll
            for (int mt = 0; mt < 2; mt++)
#pragma unroll
                for (int nt = 0; nt < 4; nt++)
                    mma_tf32(c[mt][nt], a[mt][0], a[mt][1], a[mt][2], a[mt][3],
                             bb[nt][0], bb[nt][1]);
        }
        __syncthreads();
    }

#pragma unroll
    for (int mt = 0; mt < 2; mt++) {
        int m = m0 + wm * 32 + mt * 16 + g;
        int b_ = m >> 11, p = m & 2047;
        size_t base = ((size_t)(b_ * NH + h)) * SEQ;
#pragma unroll
        for (int nt = 0; nt < 4; nt++) {
            int col = wn * 32 + nt * 8 + 2 * t;
            float bx = bias[col], by = bias[col + 1];
            float2 v0 = { c[mt][nt][0] + bx, c[mt][nt][1] + by };
            float2 v1 = { c[mt][nt][2] + bx, c[mt][nt][3] + by };
            *(float2*)&Out[(base + p) * DH + col]     = v0;
            *(float2*)&Out[(base + p + 8) * DH + col] = v1;
        }
    }
}

// ---------------------------------------------------------------------------
// Causal flash attention with tf32 mma. Block = 128 q-rows, 8 warps (16 rows
// each). K/V tiles of 64 s-positions staged in smem. Q fragments in registers
// with 1/sqrt(64) folded in. P transposed C->A layout via quad shuffles.
// ---------------------------------------------------------------------------
__global__ __launch_bounds__(256) void attn_kernel()
{
    const int qt = blockIdx.x;
    const int bh = blockIdx.y;
    const int q0 = qt * 128;
    const int b  = bh / NH, h = bh % NH;

    const float* qp = g_q + (size_t)bh * SEQ * DH;
    const float* kp = g_k + (size_t)bh * SEQ * DH;
    const float* vp = g_v + (size_t)bh * SEQ * DH;

    __shared__ float Ks[64][68];   // [s][d] : b0=Ks[8nt+g][8kt+t] -> banks 4g+t
    __shared__ float Vs[64][72];   // [s][d] : b0=Vs[8kt+t][8nt+g] -> banks 8t+g

    const int tid  = threadIdx.x;
    const int lane = tid & 31;
    const int w    = tid >> 5;   // warp 0..7, rows w*16..w*16+15
    const int g    = lane >> 2;
    const int t    = lane & 3;

    // Preload Q fragments (scaled)
    uint32_t qa[8][4];
    {
        const float* qr0 = qp + (size_t)(q0 + w * 16 + g) * DH;
        const float* qr1 = qr0 + 8 * DH;
#pragma unroll
        for (int kt = 0; kt < 8; kt++) {
            qa[kt][0] = f2tf(qr0[kt * 8 + t] * 0.125f);
            qa[kt][1] = f2tf(qr1[kt * 8 + t] * 0.125f);
            qa[kt][2] = f2tf(qr0[kt * 8 + t + 4] * 0.125f);
            qa[kt][3] = f2tf(qr1[kt * 8 + t + 4] * 0.125f);
        }
    }

    float o[8][4];
#pragma unroll
    for (int nt = 0; nt < 8; nt++)
#pragma unroll
        for (int i = 0; i < 4; i++) o[nt][i] = 0.f;
    float m0r = -1e30f, m1r = -1e30f, l0 = 0.f, l1 = 0.f;

    const int row0 = q0 + w * 16 + g;
    const int row1 = row0 + 8;

    const int nkt = q0 / 64 + 2;
    for (int kt2 = 0; kt2 < nkt; kt2++) {
        const int k0 = kt2 * 64;
        __syncthreads();
#pragma unroll
        for (int i = 0; i < 4; i++) {
            int lin = tid + i * 256;
            int row = lin >> 4;
            int c4  = lin & 15;
            float4 kv = *(const float4*)&kp[(size_t)(k0 + row) * DH + c4 * 4];
            Ks[row][c4 * 4 + 0] = f2tff(kv.x);
            Ks[row][c4 * 4 + 1] = f2tff(kv.y);
            Ks[row][c4 * 4 + 2] = f2tff(kv.z);
            Ks[row][c4 * 4 + 3] = f2tff(kv.w);
            float4 vv = *(const float4*)&vp[(size_t)(k0 + row) * DH + c4 * 4];
            Vs[row][c4 * 4 + 0] = f2tff(vv.x);
            Vs[row][c4 * 4 + 1] = f2tff(vv.y);
            Vs[row][c4 * 4 + 2] = f2tff(vv.z);
            Vs[row][c4 * 4 + 3] = f2tff(vv.w);
        }
        __syncthreads();

        // S = (Q/8) @ K^T  — fragments s[nt] cover s-cols k0+nt*8..+7
        float s[8][4];
#pragma unroll
        for (int nt = 0; nt < 8; nt++) {
            s[nt][0] = s[nt][1] = s[nt][2] = s[nt][3] = 0.f;
        }
#pragma unroll
        for (int kt = 0; kt < 8; kt++) {
#pragma unroll
            for (int nt = 0; nt < 8; nt++) {
                uint32_t b0 = __float_as_uint(Ks[nt * 8 + g][kt * 8 + t]);
                uint32_t b1 = __float_as_uint(Ks[nt * 8 + g][kt * 8 + t + 4]);
                mma_tf32(s[nt], qa[kt][0], qa[kt][1], qa[kt][2], qa[kt][3], b0, b1);
            }
        }

        // causal mask (only near diagonal)
        if (k0 + 63 > q0) {
#pragma unroll
            for (int nt = 0; nt < 8; nt++) {
                int col = k0 + nt * 8 + 2 * t;
                if (col > row0)     s[nt][0] = -1e30f;
                if (col + 1 > row0) s[nt][1] = -1e30f;
                if (col > row1)     s[nt][2] = -1e30f;
                if (col + 1 > row1) s[nt][3] = -1e30f;
            }
        }

        // online softmax (rows row0, row1; 4 lanes per row)
        float mx0 = -1e30f, mx1 = -1e30f;
#pragma unroll
        for (int nt = 0; nt < 8; nt++) {
            mx0 = fmaxf(mx0, fmaxf(s[nt][0], s[nt][1]));
            mx1 = fmaxf(mx1, fmaxf(s[nt][2], s[nt][3]));
        }
        mx0 = fmaxf(mx0, __shfl_xor_sync(0xffffffffu, mx0, 1));
        mx0 = fmaxf(mx0, __shfl_xor_sync(0xffffffffu, mx0, 2));
        mx1 = fmaxf(mx1, __shfl_xor_sync(0xffffffffu, mx1, 1));
        mx1 = fmaxf(mx1, __shfl_xor_sync(0xffffffffu, mx1, 2));

        const float m0n = fmaxf(m0r, mx0);
        const float m1n = fmaxf(m1r, mx1);
        const float sc0 = __expf(m0r - m0n);
        const float sc1 = __expf(m1r - m1n);
        m0r = m0n; m1r = m1n;

        float r0 = 0.f, r1 = 0.f;
#pragma unroll
        for (int nt = 0; nt < 8; nt++) {
            s[nt][0] = __expf(s[nt][0] - m0n);
            s[nt][1] = __expf(s[nt][1] - m0n);
            s[nt][2] = __expf(s[nt][2] - m1n);
            s[nt][3] = __expf(s[nt][3] - m1n);
            r0 += s[nt][0] + s[nt][1];
            r1 += s[nt][2] + s[nt][3];
        }
        r0 += __shfl_xor_sync(0xffffffffu, r0, 1);
        r0 += __shfl_xor_sync(0xffffffffu, r0, 2);
        r1 += __shfl_xor_sync(0xffffffffu, r1, 1);
        r1 += __shfl_xor_sync(0xffffffffu, r1, 2);
        l0 = l0 * sc0 + r0;
        l1 = l1 * sc1 + r1;

#pragma unroll
        for (int nt = 0; nt < 8; nt++) {
            o[nt][0] *= sc0; o[nt][1] *= sc0;
            o[nt][2] *= sc1; o[nt][3] *= sc1;
        }

        // O += P @ V. Transpose P (C layout -> A layout) via quad shuffles.
        const int s0l = (lane & ~3) | (t >> 1);
        const int s1l = s0l + 2;
        const bool e  = (t & 1);
#pragma unroll
        for (int kt = 0; kt < 8; kt++) {
            float v00 = __shfl_sync(0xffffffffu, s[kt][0], s0l);
            float v01 = __shfl_sync(0xffffffffu, s[kt][1], s0l);
            float v10 = __shfl_sync(0xffffffffu, s[kt][2], s0l);
            float v11 = __shfl_sync(0xffffffffu, s[kt][3], s0l);
            float w00 = __shfl_sync(0xffffffffu, s[kt][0], s1l);
            float w01 = __shfl_sync(0xffffffffu, s[kt][1], s1l);
            float w10 = __shfl_sync(0xffffffffu, s[kt][2], s1l);
            float w11 = __shfl_sync(0xffffffffu, s[kt][3], s1l);
            uint32_t pa0 = f2tf(e ? v01 : v00);
            uint32_t pa1 = f2tf(e ? v11 : v10);
            uint32_t pa2 = f2tf(e ? w01 : w00);
            uint32_t pa3 = f2tf(e ? w11 : w10);
#pragma unroll
            for (int nt = 0; nt < 8; nt++) {
                uint32_t b0 = __float_as_uint(Vs[kt * 8 + t][nt * 8 + g]);
                uint32_t b1 = __float_as_uint(Vs[kt * 8 + t + 4][nt * 8 + g]);
                mma_tf32(o[nt], pa0, pa1, pa2, pa3, b0, b1);
            }
        }
    }

    const float inv0 = 1.f / l0;
    const float inv1 = 1.f / l1;
    float* or0 = g_o + ((size_t)(b * SEQ) + row0) * DM + h * DH;
    float* or1 = or0 + (size_t)8 * DM;
#pragma unroll
    for (int nt = 0; nt < 8; nt++) {
        int col = nt * 8 + 2 * t;
        float2 v0 = { o[nt][0] * inv0, o[nt][1] * inv0 };
        float2 v1 = { o[nt][2] * inv1, o[nt][3] * inv1 };
        *(float2*)&or0[col] = v0;
        *(float2*)&or1[col] = v1;
    }
}

// ---------------------------------------------------------------------------
// Output projection: tf32 GEMM, out[m,n] = sum_k g_o[m,k]*Ow[k,n] + Ob[n]
// ---------------------------------------------------------------------------
__global__ __launch_bounds__(256) void oproj_kernel(
    const float* __restrict__ Ow, const float* __restrict__ Ob,
    float* __restrict__ out)
{
    const int m0 = blockIdx.x * 128;
    const int n0 = blockIdx.y * 64;

    __shared__ float As[128][36];
    __shared__ float Bs[32][72];

    const int tid  = threadIdx.x;
    const int lane = tid & 31;
    const int w    = tid >> 5;
    const int wm   = w >> 1;
    const int wn   = w & 1;
    const int g    = lane >> 2;
    const int t    = lane & 3;

    float c[2][4][4];
#pragma unroll
    for (int mt = 0; mt < 2; mt++)
#pragma unroll
        for (int nt = 0; nt < 4; nt++)
#pragma unroll
            for (int i = 0; i < 4; i++) c[mt][nt][i] = 0.f;

    for (int k0 = 0; k0 < DM; k0 += 32) {
#pragma unroll
        for (int i = 0; i < 4; i++) {
            int lin = tid + i * 256;
            int row = lin >> 3;
            int c4  = lin & 7;
            float4 v = *(const float4*)&g_o[(size_t)(m0 + row) * DM + k0 + c4 * 4];
            As[row][c4 * 4 + 0] = f2tff(v.x);
            As[row][c4 * 4 + 1] = f2tff(v.y);
            As[row][c4 * 4 + 2] = f2tff(v.z);
            As[row][c4 * 4 + 3] = f2tff(v.w);
        }
#pragma unroll
        for (int i = 0; i < 2; i++) {
            int lin = tid + i * 256;
            int row = lin >> 4;
            int c4  = lin & 15;
            float4 v = *(const float4*)&Ow[(size_t)(k0 + row) * DM + n0 + c4 * 4];
            Bs[row][c4 * 4 + 0] = f2tff(v.x);
            Bs[row][c4 * 4 + 1] = f2tff(v.y);
            Bs[row][c4 * 4 + 2] = f2tff(v.z);
            Bs[row][c4 * 4 + 3] = f2tff(v.w);
        }
        __syncthreads();

#pragma unroll
        for (int ks = 0; ks < 4; ks++) {
            uint32_t a[2][4], bb[4][2];
#pragma unroll
            for (int mt = 0; mt < 2; mt++) {
                int r0 = wm * 32 + mt * 16 + g;
                a[mt][0] = __float_as_uint(As[r0][ks * 8 + t]);
                a[mt][1] = __float_as_uint(As[r0 + 8][ks * 8 + t]);
                a[mt][2] = __float_as_uint(As[r0][ks * 8 + t + 4]);
                a[mt][3] = __float_as_uint(As[r0 + 8][ks * 8 + t + 4]);
            }
#pragma unroll
            for (int nt = 0; nt < 4; nt++) {
                int col = wn * 32 + nt * 8 + g;
                bb[nt][0] = __float_as_uint(Bs[ks * 8 + t][col]);
                bb[nt][1] = __float_as_uint(Bs[ks * 8 + t + 4][col]);
            }
#pragma unroll
            for (int mt = 0; mt < 2; mt++)
#pragma unroll
                for (int nt = 0; nt < 4; nt++)
                    mma_tf32(c[mt][nt], a[mt][0], a[mt][1], a[mt][2], a[mt][3],
                             bb[nt][0], bb[nt][1]);
        }
        __syncthreads();
    }

#pragma unroll
    for (int mt = 0; mt < 2; mt++) {
        int m = m0 + wm * 32 + mt * 16 + g;
#pragma unroll
        for (int nt = 0; nt < 4; nt++) {
            int col = n0 + wn * 32 + nt * 8 + 2 * t;
            float bx = Ob[col], by = Ob[col + 1];
            float2 v0 = { c[mt][nt][0] + bx, c[mt][nt][1] + by };
            float2 v1 = { c[mt][nt][2] + bx, c[mt][nt][3] + by };
            *(float2*)&out[(size_t)m * DM + col]       = v0;
            *(float2*)&out[(size_t)(m + 8) * DM + col] = v1;
        }
    }
}

extern "C" void kernel_launch(void* const* d_in, const int* in_sizes, int n_in,
                              void* d_out, int out_size)
{
    const float* x  = (const float*)d_in[0];
    const float* Qw = (const float*)d_in[1];
    const float* Qb = (const float*)d_in[2];
    const float* Kw = (const float*)d_in[3];
    const float* Kb = (const float*)d_in[4];
    const float* Vw = (const float*)d_in[5];
    const float* Vb = (const float*)d_in[6];
    const float* Ow = (const float*)d_in[7];
    const float* Ob = (const float*)d_in[8];
    float* out = (float*)d_out;

    qkv_kernel<<<dim3(MROWS / 128, NH, 3), 256>>>(x, Qw, Qb, Kw, Kb, Vw, Vb);
    attn_kernel<<<dim3(SEQ / 128, BATCH * NH), 256>>>();
    oproj_kernel<<<dim3(MROWS / 128, DM / 64), 256>>>(Ow, Ob, out);
}

// round 6
// speedup vs baseline: 1.6780x; 1.6780x over previous
#include <cuda_runtime.h>
#include <cstdint>

#define BATCH 4
#define SEQ   2048
#define NH    16
#define DH    64
#define DM    1024
#define MROWS (BATCH*SEQ)

__device__ float g_q[(size_t)BATCH*NH*SEQ*DH];
__device__ float g_k[(size_t)BATCH*NH*SEQ*DH];
__device__ float g_v[(size_t)BATCH*NH*SEQ*DH];
__device__ float g_o[(size_t)MROWS*DM];

__device__ __forceinline__ uint32_t f2tf(float x) {
    uint32_t u;
    asm("cvt.rna.tf32.f32 %0, %1;" : "=r"(u) : "f"(x));
    return u;
}
__device__ __forceinline__ float f2tff(float x) { return __uint_as_float(f2tf(x)); }

__device__ __forceinline__ void mma_tf32(float* c,
    uint32_t a0, uint32_t a1, uint32_t a2, uint32_t a3,
    uint32_t b0, uint32_t b1)
{
    asm volatile(
        "mma.sync.aligned.m16n8k8.row.col.f32.tf32.tf32.f32 "
        "{%0,%1,%2,%3}, {%4,%5,%6,%7}, {%8,%9}, {%0,%1,%2,%3};"
        : "+f"(c[0]), "+f"(c[1]), "+f"(c[2]), "+f"(c[3])
        : "r"(a0), "r"(a1), "r"(a2), "r"(a3), "r"(b0), "r"(b1));
}

// ---------------------------------------------------------------------------
// QKV projection: tf32 GEMM 128x64 tile, register-prefetch pipeline.
// ---------------------------------------------------------------------------
__global__ __launch_bounds__(256) void qkv_kernel(
    const float* __restrict__ X,
    const float* __restrict__ Qw, const float* __restrict__ Qb,
    const float* __restrict__ Kw, const float* __restrict__ Kb,
    const float* __restrict__ Vw, const float* __restrict__ Vb)
{
    const int m0    = blockIdx.x * 128;
    const int h     = blockIdx.y;
    const int which = blockIdx.z;

    const float* W    = (which == 0 ? Qw : which == 1 ? Kw : Vw) + (size_t)h * DM * DH;
    const float* bias = (which == 0 ? Qb : which == 1 ? Kb : Vb) + h * DH;
    float* Out        = (which == 0 ? g_q : which == 1 ? g_k : g_v);

    __shared__ float As[128][36];
    __shared__ float Bs[32][72];

    const int tid  = threadIdx.x;
    const int lane = tid & 31;
    const int w    = tid >> 5;
    const int wm   = w >> 1;
    const int wn   = w & 1;
    const int g    = lane >> 2;
    const int t    = lane & 3;

    float c[2][4][4];
#pragma unroll
    for (int mt = 0; mt < 2; mt++)
#pragma unroll
        for (int nt = 0; nt < 4; nt++)
#pragma unroll
            for (int i = 0; i < 4; i++) c[mt][nt][i] = 0.f;

    float4 areg[4], breg[2];
#pragma unroll
    for (int i = 0; i < 4; i++) {
        int lin = tid + i * 256, row = lin >> 3, c4 = lin & 7;
        areg[i] = *(const float4*)&X[(size_t)(m0 + row) * DM + c4 * 4];
    }
#pragma unroll
    for (int i = 0; i < 2; i++) {
        int lin = tid + i * 256, row = lin >> 4, c4 = lin & 15;
        breg[i] = *(const float4*)&W[(size_t)row * DH + c4 * 4];
    }

    for (int k0 = 0; k0 < DM; k0 += 32) {
#pragma unroll
        for (int i = 0; i < 4; i++) {
            int lin = tid + i * 256, row = lin >> 3, c4 = lin & 7;
            As[row][c4 * 4 + 0] = f2tff(areg[i].x);
            As[row][c4 * 4 + 1] = f2tff(areg[i].y);
            As[row][c4 * 4 + 2] = f2tff(areg[i].z);
            As[row][c4 * 4 + 3] = f2tff(areg[i].w);
        }
#pragma unroll
        for (int i = 0; i < 2; i++) {
            int lin = tid + i * 256, row = lin >> 4, c4 = lin & 15;
            Bs[row][c4 * 4 + 0] = f2tff(breg[i].x);
            Bs[row][c4 * 4 + 1] = f2tff(breg[i].y);
            Bs[row][c4 * 4 + 2] = f2tff(breg[i].z);
            Bs[row][c4 * 4 + 3] = f2tff(breg[i].w);
        }
        __syncthreads();

        if (k0 + 32 < DM) {
            const int kn = k0 + 32;
#pragma unroll
            for (int i = 0; i < 4; i++) {
                int lin = tid + i * 256, row = lin >> 3, c4 = lin & 7;
                areg[i] = *(const float4*)&X[(size_t)(m0 + row) * DM + kn + c4 * 4];
            }
#pragma unroll
            for (int i = 0; i < 2; i++) {
                int lin = tid + i * 256, row = lin >> 4, c4 = lin & 15;
                breg[i] = *(const float4*)&W[(size_t)(kn + row) * DH + c4 * 4];
            }
        }

#pragma unroll
        for (int ks = 0; ks < 4; ks++) {
            uint32_t a[2][4], bb[4][2];
#pragma unroll
            for (int mt = 0; mt < 2; mt++) {
                int r0 = wm * 32 + mt * 16 + g;
                a[mt][0] = __float_as_uint(As[r0][ks * 8 + t]);
                a[mt][1] = __float_as_uint(As[r0 + 8][ks * 8 + t]);
                a[mt][2] = __float_as_uint(As[r0][ks * 8 + t + 4]);
                a[mt][3] = __float_as_uint(As[r0 + 8][ks * 8 + t + 4]);
            }
#pragma unroll
            for (int nt = 0; nt < 4; nt++) {
                int col = wn * 32 + nt * 8 + g;
                bb[nt][0] = __float_as_uint(Bs[ks * 8 + t][col]);
                bb[nt][1] = __float_as_uint(Bs[ks * 8 + t + 4][col]);
            }
#pragma unroll
            for (int mt = 0; mt < 2; mt++)
#pragma unroll
                for (int nt = 0; nt < 4; nt++)
                    mma_tf32(c[mt][nt], a[mt][0], a[mt][1], a[mt][2], a[mt][3],
                             bb[nt][0], bb[nt][1]);
        }
        __syncthreads();
    }

#pragma unroll
    for (int mt = 0; mt < 2; mt++) {
        int m = m0 + wm * 32 + mt * 16 + g;
        int b_ = m >> 11, p = m & 2047;
        size_t base = ((size_t)(b_ * NH + h)) * SEQ;
#pragma unroll
        for (int nt = 0; nt < 4; nt++) {
            int col = wn * 32 + nt * 8 + 2 * t;
            float bx = bias[col], by = bias[col + 1];
            float2 v0 = { c[mt][nt][0] + bx, c[mt][nt][1] + by };
            float2 v1 = { c[mt][nt][2] + bx, c[mt][nt][3] + by };
            *(float2*)&Out[(base + p) * DH + col]     = v0;
            *(float2*)&Out[(base + p + 8) * DH + col] = v1;
        }
    }
}

// ---------------------------------------------------------------------------
// Causal flash attention, tf32 mma, register-prefetch K/V pipeline.
// ---------------------------------------------------------------------------
__global__ __launch_bounds__(256) void attn_kernel()
{
    const int qt = (SEQ / 128 - 1) - blockIdx.x;   // longest blocks first
    const int bh = blockIdx.y;
    const int q0 = qt * 128;
    const int b  = bh / NH, h = bh % NH;

    const float* qp = g_q + (size_t)bh * SEQ * DH;
    const float* kp = g_k + (size_t)bh * SEQ * DH;
    const float* vp = g_v + (size_t)bh * SEQ * DH;

    __shared__ float Ks[64][68];
    __shared__ float Vs[64][72];

    const int tid  = threadIdx.x;
    const int lane = tid & 31;
    const int w    = tid >> 5;
    const int g    = lane >> 2;
    const int t    = lane & 3;

    uint32_t qa[8][4];
    {
        const float* qr0 = qp + (size_t)(q0 + w * 16 + g) * DH;
        const float* qr1 = qr0 + 8 * DH;
#pragma unroll
        for (int kt = 0; kt < 8; kt++) {
            qa[kt][0] = f2tf(qr0[kt * 8 + t] * 0.125f);
            qa[kt][1] = f2tf(qr1[kt * 8 + t] * 0.125f);
            qa[kt][2] = f2tf(qr0[kt * 8 + t + 4] * 0.125f);
            qa[kt][3] = f2tf(qr1[kt * 8 + t + 4] * 0.125f);
        }
    }

    float o[8][4];
#pragma unroll
    for (int nt = 0; nt < 8; nt++) { o[nt][0]=o[nt][1]=o[nt][2]=o[nt][3]=0.f; }
    float m0r = -1e30f, m1r = -1e30f, l0 = 0.f, l1 = 0.f;
    const int row0 = q0 + w * 16 + g, row1 = row0 + 8;

    const int ldr = tid >> 4, ldc = tid & 15;   // row 0..15 (x4), col float4

    float4 kreg[4], vreg[4];
#pragma unroll
    for (int i = 0; i < 4; i++) {
        int row = ldr + i * 16;
        kreg[i] = *(const float4*)&kp[(size_t)row * DH + ldc * 4];
        vreg[i] = *(const float4*)&vp[(size_t)row * DH + ldc * 4];
    }

    const int nkt = q0 / 64 + 2;
    for (int kt2 = 0; kt2 < nkt; kt2++) {
        const int k0 = kt2 * 64;
#pragma unroll
        for (int i = 0; i < 4; i++) {
            int row = ldr + i * 16;
            Ks[row][ldc*4+0]=f2tff(kreg[i].x); Ks[row][ldc*4+1]=f2tff(kreg[i].y);
            Ks[row][ldc*4+2]=f2tff(kreg[i].z); Ks[row][ldc*4+3]=f2tff(kreg[i].w);
            Vs[row][ldc*4+0]=f2tff(vreg[i].x); Vs[row][ldc*4+1]=f2tff(vreg[i].y);
            Vs[row][ldc*4+2]=f2tff(vreg[i].z); Vs[row][ldc*4+3]=f2tff(vreg[i].w);
        }
        __syncthreads();

        if (kt2 + 1 < nkt) {
            const int kn = k0 + 64;
#pragma unroll
            for (int i = 0; i < 4; i++) {
                int row = kn + ldr + i * 16;
                kreg[i] = *(const float4*)&kp[(size_t)row * DH + ldc * 4];
                vreg[i] = *(const float4*)&vp[(size_t)row * DH + ldc * 4];
            }
        }

        float s[8][4];
#pragma unroll
        for (int nt = 0; nt < 8; nt++) { s[nt][0]=s[nt][1]=s[nt][2]=s[nt][3]=0.f; }
#pragma unroll
        for (int kt = 0; kt < 8; kt++)
#pragma unroll
            for (int nt = 0; nt < 8; nt++) {
                uint32_t b0 = __float_as_uint(Ks[nt * 8 + g][kt * 8 + t]);
                uint32_t b1 = __float_as_uint(Ks[nt * 8 + g][kt * 8 + t + 4]);
                mma_tf32(s[nt], qa[kt][0], qa[kt][1], qa[kt][2], qa[kt][3], b0, b1);
            }

        if (k0 + 63 > q0) {
#pragma unroll
            for (int nt = 0; nt < 8; nt++) {
                int col = k0 + nt * 8 + 2 * t;
                if (col > row0)     s[nt][0] = -1e30f;
                if (col + 1 > row0) s[nt][1] = -1e30f;
                if (col > row1)     s[nt][2] = -1e30f;
                if (col + 1 > row1) s[nt][3] = -1e30f;
            }
        }

        float mx0 = -1e30f, mx1 = -1e30f;
#pragma unroll
        for (int nt = 0; nt < 8; nt++) {
            mx0 = fmaxf(mx0, fmaxf(s[nt][0], s[nt][1]));
            mx1 = fmaxf(mx1, fmaxf(s[nt][2], s[nt][3]));
        }
        mx0 = fmaxf(mx0, __shfl_xor_sync(~0u, mx0, 1));
        mx0 = fmaxf(mx0, __shfl_xor_sync(~0u, mx0, 2));
        mx1 = fmaxf(mx1, __shfl_xor_sync(~0u, mx1, 1));
        mx1 = fmaxf(mx1, __shfl_xor_sync(~0u, mx1, 2));

        const float m0n = fmaxf(m0r, mx0), m1n = fmaxf(m1r, mx1);
        const float sc0 = __expf(m0r - m0n), sc1 = __expf(m1r - m1n);
        m0r = m0n; m1r = m1n;

        float r0 = 0.f, r1 = 0.f;
#pragma unroll
        for (int nt = 0; nt < 8; nt++) {
            s[nt][0] = __expf(s[nt][0] - m0n); s[nt][1] = __expf(s[nt][1] - m0n);
            s[nt][2] = __expf(s[nt][2] - m1n); s[nt][3] = __expf(s[nt][3] - m1n);
            r0 += s[nt][0] + s[nt][1]; r1 += s[nt][2] + s[nt][3];
        }
        r0 += __shfl_xor_sync(~0u, r0, 1); r0 += __shfl_xor_sync(~0u, r0, 2);
        r1 += __shfl_xor_sync(~0u, r1, 1); r1 += __shfl_xor_sync(~0u, r1, 2);
        l0 = l0 * sc0 + r0; l1 = l1 * sc1 + r1;

#pragma unroll
        for (int nt = 0; nt < 8; nt++) {
            o[nt][0] *= sc0; o[nt][1] *= sc0; o[nt][2] *= sc1; o[nt][3] *= sc1;
        }

        const int s0l = (lane & ~3) | (t >> 1), s1l = s0l + 2;
        const bool e = (t & 1);
#pragma unroll
        for (int kt = 0; kt < 8; kt++) {
            float v00 = __shfl_sync(~0u, s[kt][0], s0l), v01 = __shfl_sync(~0u, s[kt][1], s0l);
            float v10 = __shfl_sync(~0u, s[kt][2], s0l), v11 = __shfl_sync(~0u, s[kt][3], s0l);
            float w00 = __shfl_sync(~0u, s[kt][0], s1l), w01 = __shfl_sync(~0u, s[kt][1], s1l);
            float w10 = __shfl_sync(~0u, s[kt][2], s1l), w11 = __shfl_sync(~0u, s[kt][3], s1l);
            uint32_t pa0 = f2tf(e ? v01 : v00), pa1 = f2tf(e ? v11 : v10);
            uint32_t pa2 = f2tf(e ? w01 : w00), pa3 = f2tf(e ? w11 : w10);
#pragma unroll
            for (int nt = 0; nt < 8; nt++) {
                uint32_t b0 = __float_as_uint(Vs[kt * 8 + t][nt * 8 + g]);
                uint32_t b1 = __float_as_uint(Vs[kt * 8 + t + 4][nt * 8 + g]);
                mma_tf32(o[nt], pa0, pa1, pa2, pa3, b0, b1);
            }
        }
        __syncthreads();
    }

    const float inv0 = 1.f / l0, inv1 = 1.f / l1;
    float* or0 = g_o + ((size_t)(b * SEQ) + row0) * DM + h * DH;
    float* or1 = or0 + (size_t)8 * DM;
#pragma unroll
    for (int nt = 0; nt < 8; nt++) {
        int col = nt * 8 + 2 * t;
        float2 v0 = { o[nt][0] * inv0, o[nt][1] * inv0 };
        float2 v1 = { o[nt][2] * inv1, o[nt][3] * inv1 };
        *(float2*)&or0[col] = v0;
        *(float2*)&or1[col] = v1;
    }
}

// ---------------------------------------------------------------------------
// Output projection: tf32 GEMM with register-prefetch pipeline.
// ---------------------------------------------------------------------------
__global__ __launch_bounds__(256) void oproj_kernel(
    const float* __restrict__ Ow, const float* __restrict__ Ob,
    float* __restrict__ out)
{
    const int m0 = blockIdx.x * 128;
    const int n0 = blockIdx.y * 64;

    __shared__ float As[128][36];
    __shared__ float Bs[32][72];

    const int tid  = threadIdx.x;
    const int lane = tid & 31;
    const int w    = tid >> 5;
    const int wm   = w >> 1;
    const int wn   = w & 1;
    const int g    = lane >> 2;
    const int t    = lane & 3;

    float c[2][4][4];
#pragma unroll
    for (int mt = 0; mt < 2; mt++)
#pragma unroll
        for (int nt = 0; nt < 4; nt++)
#pragma unroll
            for (int i = 0; i < 4; i++) c[mt][nt][i] = 0.f;

    float4 areg[4], breg[2];
#pragma unroll
    for (int i = 0; i < 4; i++) {
        int lin = tid + i * 256, row = lin >> 3, c4 = lin & 7;
        areg[i] = *(const float4*)&g_o[(size_t)(m0 + row) * DM + c4 * 4];
    }
#pragma unroll
    for (int i = 0; i < 2; i++) {
        int lin = tid + i * 256, row = lin >> 4, c4 = lin & 15;
        breg[i] = *(const float4*)&Ow[(size_t)row * DM + n0 + c4 * 4];
    }

    for (int k0 = 0; k0 < DM; k0 += 32) {
#pragma unroll
        for (int i = 0; i < 4; i++) {
            int lin = tid + i * 256, row = lin >> 3, c4 = lin & 7;
            As[row][c4 * 4 + 0] = f2tff(areg[i].x);
            As[row][c4 * 4 + 1] = f2tff(areg[i].y);
            As[row][c4 * 4 + 2] = f2tff(areg[i].z);
            As[row][c4 * 4 + 3] = f2tff(areg[i].w);
        }
#pragma unroll
        for (int i = 0; i < 2; i++) {
            int lin = tid + i * 256, row = lin >> 4, c4 = lin & 15;
            Bs[row][c4 * 4 + 0] = f2tff(breg[i].x);
            Bs[row][c4 * 4 + 1] = f2tff(breg[i].y);
            Bs[row][c4 * 4 + 2] = f2tff(breg[i].z);
            Bs[row][c4 * 4 + 3] = f2tff(breg[i].w);
        }
        __syncthreads();

        if (k0 + 32 < DM) {
            const int kn = k0 + 32;
#pragma unroll
            for (int i = 0; i < 4; i++) {
                int lin = tid + i * 256, row = lin >> 3, c4 = lin & 7;
                areg[i] = *(const float4*)&g_o[(size_t)(m0 + row) * DM + kn + c4 * 4];
            }
#pragma unroll
            for (int i = 0; i < 2; i++) {
                int lin = tid + i * 256, row = lin >> 4, c4 = lin & 15;
                breg[i] = *(const float4*)&Ow[(size_t)(kn + row) * DM + n0 + c4 * 4];
            }
        }

#pragma unroll
        for (int ks = 0; ks < 4; ks++) {
            uint32_t a[2][4], bb[4][2];
#pragma unroll
            for (int mt = 0; mt < 2; mt++) {
                int r0 = wm * 32 + mt * 16 + g;
                a[mt][0] = __float_as_uint(As[r0][ks * 8 + t]);
                a[mt][1] = __float_as_uint(As[r0 + 8][ks * 8 + t]);
                a[mt][2] = __float_as_uint(As[r0][ks * 8 + t + 4]);
                a[mt][3] = __float_as_uint(As[r0 + 8][ks * 8 + t + 4]);
            }
#pragma unroll
            for (int nt = 0; nt < 4; nt++) {
                int col = wn * 32 + nt * 8 + g;
                bb[nt][0] = __float_as_uint(Bs[ks * 8 + t][col]);
                bb[nt][1] = __float_as_uint(Bs[ks * 8 + t + 4][col]);
            }
#pragma unroll
            for (int mt = 0; mt < 2; mt++)
#pragma unroll
                for (int nt = 0; nt < 4; nt++)
                    mma_tf32(c[mt][nt], a[mt][0], a[mt][1], a[mt][2], a[mt][3],
                             bb[nt][0], bb[nt][1]);
        }
        __syncthreads();
    }

#pragma unroll
    for (int mt = 0; mt < 2; mt++) {
        int m = m0 + wm * 32 + mt * 16 + g;
#pragma unroll
        for (int nt = 0; nt < 4; nt++) {
            int col = n0 + wn * 32 + nt * 8 + 2 * t;
            float bx = Ob[col], by = Ob[col + 1];
            float2 v0 = { c[mt][nt][0] + bx, c[mt][nt][1] + by };
            float2 v1 = { c[mt][nt][2] + bx, c[mt][nt][3] + by };
            *(float2*)&out[(size_t)m * DM + col]       = v0;
            *(float2*)&out[(size_t)(m + 8) * DM + col] = v1;
        }
    }
}

extern "C" void kernel_launch(void* const* d_in, const int* in_sizes, int n_in,
                              void* d_out, int out_size)
{
    const float* x  = (const float*)d_in[0];
    const float* Qw = (const float*)d_in[1];
    const float* Qb = (const float*)d_in[2];
    const float* Kw = (const float*)d_in[3];
    const float* Kb = (const float*)d_in[4];
    const float* Vw = (const float*)d_in[5];
    const float* Vb = (const float*)d_in[6];
    const float* Ow = (const float*)d_in[7];
    const float* Ob = (const float*)d_in[8];
    float* out = (float*)d_out;

    qkv_kernel<<<dim3(MROWS / 128, NH, 3), 256>>>(x, Qw, Qb, Kw, Kb, Vw, Vb);
    attn_kernel<<<dim3(SEQ / 128, BATCH * NH), 256>>>();
    oproj_kernel<<<dim3(MROWS / 128, DM / 64), 256>>>(Ow, Ob, out);
}

// round 7
// speedup vs baseline: 1.8444x; 1.0992x over previous
#include <cuda_runtime.h>
#include <cstdint>

#define BATCH 4
#define SEQ   2048
#define NH    16
#define DH    64
#define DM    1024
#define MROWS (BATCH*SEQ)

__device__ float g_q[(size_t)BATCH*NH*SEQ*DH];
__device__ float g_k[(size_t)BATCH*NH*SEQ*DH];
__device__ float g_v[(size_t)BATCH*NH*SEQ*DH];
__device__ float g_o[(size_t)MROWS*DM];

__device__ __forceinline__ uint32_t f2tf(float x) {
    uint32_t u;
    asm("cvt.rna.tf32.f32 %0, %1;" : "=r"(u) : "f"(x));
    return u;
}
__device__ __forceinline__ float f2tff(float x) { return __uint_as_float(f2tf(x)); }

__device__ __forceinline__ void mma_tf32(float* c,
    uint32_t a0, uint32_t a1, uint32_t a2, uint32_t a3,
    uint32_t b0, uint32_t b1)
{
    asm volatile(
        "mma.sync.aligned.m16n8k8.row.col.f32.tf32.tf32.f32 "
        "{%0,%1,%2,%3}, {%4,%5,%6,%7}, {%8,%9}, {%0,%1,%2,%3};"
        : "+f"(c[0]), "+f"(c[1]), "+f"(c[2]), "+f"(c[3])
        : "r"(a0), "r"(a1), "r"(a2), "r"(a3), "r"(b0), "r"(b1));
}

// ---------------------------------------------------------------------------
// QKV projection: 128x128 tile (2 heads), 8 warps of 32x64, reg prefetch.
// ---------------------------------------------------------------------------
__global__ __launch_bounds__(256) void qkv_kernel(
    const float* __restrict__ X,
    const float* __restrict__ Qw, const float* __restrict__ Qb,
    const float* __restrict__ Kw, const float* __restrict__ Kb,
    const float* __restrict__ Vw, const float* __restrict__ Vb)
{
    const int m0    = blockIdx.x * 128;
    const int hp    = blockIdx.y;          // head pair
    const int which = blockIdx.z;

    const float* W    = (which == 0 ? Qw : which == 1 ? Kw : Vw);
    const float* bias = (which == 0 ? Qb : which == 1 ? Kb : Vb);
    float* Out        = (which == 0 ? g_q : which == 1 ? g_k : g_v);

    __shared__ float As[128][36];    // [m][k]  a-frag banks 4g+t
    __shared__ float Bs[32][136];    // [k][n]  b-frag banks 8t+g

    const int tid  = threadIdx.x;
    const int lane = tid & 31;
    const int w    = tid >> 5;
    const int wm   = w >> 1;     // 0..3
    const int wn   = w & 1;      // 0..1
    const int g    = lane >> 2;
    const int t    = lane & 3;

    float c[2][8][4];
#pragma unroll
    for (int mt = 0; mt < 2; mt++)
#pragma unroll
        for (int nt = 0; nt < 8; nt++)
#pragma unroll
            for (int i = 0; i < 4; i++) c[mt][nt][i] = 0.f;

    // A: 128x32 = 1024 float4, 4/thread.  B: 32x128 = 1024 float4, 4/thread.
    const int arow = tid >> 3, ac4 = tid & 7;        // +i*32 rows
    const int brow = tid >> 5, bc4 = tid & 31;       // +i*8 rows
    const int bh   = 2 * hp + (bc4 >> 4);            // head for my B column
    const int bd   = (bc4 & 15) * 4;

    float4 areg[4], breg[4];
#pragma unroll
    for (int i = 0; i < 4; i++) {
        areg[i] = *(const float4*)&X[(size_t)(m0 + arow + i * 32) * DM + ac4 * 4];
        breg[i] = *(const float4*)&W[((size_t)bh * DM + brow + i * 8) * DH + bd];
    }

    for (int k0 = 0; k0 < DM; k0 += 32) {
#pragma unroll
        for (int i = 0; i < 4; i++) {
            int row = arow + i * 32;
            As[row][ac4 * 4 + 0] = f2tff(areg[i].x);
            As[row][ac4 * 4 + 1] = f2tff(areg[i].y);
            As[row][ac4 * 4 + 2] = f2tff(areg[i].z);
            As[row][ac4 * 4 + 3] = f2tff(areg[i].w);
            int rb = brow + i * 8;
            Bs[rb][bc4 * 4 + 0] = f2tff(breg[i].x);
            Bs[rb][bc4 * 4 + 1] = f2tff(breg[i].y);
            Bs[rb][bc4 * 4 + 2] = f2tff(breg[i].z);
            Bs[rb][bc4 * 4 + 3] = f2tff(breg[i].w);
        }
        __syncthreads();

        if (k0 + 32 < DM) {
            const int kn = k0 + 32;
#pragma unroll
            for (int i = 0; i < 4; i++) {
                areg[i] = *(const float4*)&X[(size_t)(m0 + arow + i * 32) * DM + kn + ac4 * 4];
                breg[i] = *(const float4*)&W[((size_t)bh * DM + kn + brow + i * 8) * DH + bd];
            }
        }

#pragma unroll
        for (int ks = 0; ks < 4; ks++) {
            uint32_t a[2][4], bb[8][2];
#pragma unroll
            for (int mt = 0; mt < 2; mt++) {
                int r0 = wm * 32 + mt * 16 + g;
                a[mt][0] = __float_as_uint(As[r0][ks * 8 + t]);
                a[mt][1] = __float_as_uint(As[r0 + 8][ks * 8 + t]);
                a[mt][2] = __float_as_uint(As[r0][ks * 8 + t + 4]);
                a[mt][3] = __float_as_uint(As[r0 + 8][ks * 8 + t + 4]);
            }
#pragma unroll
            for (int nt = 0; nt < 8; nt++) {
                int col = wn * 64 + nt * 8 + g;
                bb[nt][0] = __float_as_uint(Bs[ks * 8 + t][col]);
                bb[nt][1] = __float_as_uint(Bs[ks * 8 + t + 4][col]);
            }
#pragma unroll
            for (int mt = 0; mt < 2; mt++)
#pragma unroll
                for (int nt = 0; nt < 8; nt++)
                    mma_tf32(c[mt][nt], a[mt][0], a[mt][1], a[mt][2], a[mt][3],
                             bb[nt][0], bb[nt][1]);
        }
        __syncthreads();
    }

    const int h = 2 * hp + wn;
    const float* bi = bias + h * DH;
#pragma unroll
    for (int mt = 0; mt < 2; mt++) {
        int m = m0 + wm * 32 + mt * 16 + g;
        int b_ = m >> 11, p = m & 2047;
        float* dst = Out + (((size_t)(b_ * NH + h)) * SEQ + p) * DH;
#pragma unroll
        for (int nt = 0; nt < 8; nt++) {
            int d = nt * 8 + 2 * t;
            float bx = bi[d], by = bi[d + 1];
            float2 v0 = { c[mt][nt][0] + bx, c[mt][nt][1] + by };
            float2 v1 = { c[mt][nt][2] + bx, c[mt][nt][3] + by };
            *(float2*)&dst[d]            = v0;
            *(float2*)&dst[8 * DH + d]   = v1;
        }
    }
}

// ---------------------------------------------------------------------------
// Causal flash attention, tf32 mma, double-buffered K/V (dynamic smem),
// register-prefetch pipeline. One __syncthreads per tile.
// ---------------------------------------------------------------------------
#define KS_ELEMS (64 * 68)
#define VS_ELEMS (64 * 72)
#define ATTN_SMEM ((2 * KS_ELEMS + 2 * VS_ELEMS) * 4)

__global__ __launch_bounds__(256) void attn_kernel()
{
    extern __shared__ float sm[];
    float* KsB = sm;                       // [2][64][68]
    float* VsB = sm + 2 * KS_ELEMS;        // [2][64][72]

    const int qt = (SEQ / 128 - 1) - blockIdx.x;
    const int bh = blockIdx.y;
    const int q0 = qt * 128;
    const int b  = bh / NH, h = bh % NH;

    const float* qp = g_q + (size_t)bh * SEQ * DH;
    const float* kp = g_k + (size_t)bh * SEQ * DH;
    const float* vp = g_v + (size_t)bh * SEQ * DH;

    const int tid  = threadIdx.x;
    const int lane = tid & 31;
    const int w    = tid >> 5;
    const int g    = lane >> 2;
    const int t    = lane & 3;

    uint32_t qa[8][4];
    {
        const float* qr0 = qp + (size_t)(q0 + w * 16 + g) * DH;
        const float* qr1 = qr0 + 8 * DH;
#pragma unroll
        for (int kt = 0; kt < 8; kt++) {
            qa[kt][0] = f2tf(qr0[kt * 8 + t] * 0.125f);
            qa[kt][1] = f2tf(qr1[kt * 8 + t] * 0.125f);
            qa[kt][2] = f2tf(qr0[kt * 8 + t + 4] * 0.125f);
            qa[kt][3] = f2tf(qr1[kt * 8 + t + 4] * 0.125f);
        }
    }

    float o[8][4];
#pragma unroll
    for (int nt = 0; nt < 8; nt++) { o[nt][0]=o[nt][1]=o[nt][2]=o[nt][3]=0.f; }
    float m0r = -1e30f, m1r = -1e30f, l0 = 0.f, l1 = 0.f;
    const int row0 = q0 + w * 16 + g, row1 = row0 + 8;

    const int ldr = tid >> 4, ldc = tid & 15;

    float4 kreg[4], vreg[4];
#pragma unroll
    for (int i = 0; i < 4; i++) {
        int row = ldr + i * 16;
        kreg[i] = *(const float4*)&kp[(size_t)row * DH + ldc * 4];
        vreg[i] = *(const float4*)&vp[(size_t)row * DH + ldc * 4];
    }
    // stage tile 0 into buffer 0
#pragma unroll
    for (int i = 0; i < 4; i++) {
        int row = ldr + i * 16;
        float* kd = KsB + row * 68 + ldc * 4;
        float* vd = VsB + row * 72 + ldc * 4;
        kd[0]=f2tff(kreg[i].x); kd[1]=f2tff(kreg[i].y); kd[2]=f2tff(kreg[i].z); kd[3]=f2tff(kreg[i].w);
        vd[0]=f2tff(vreg[i].x); vd[1]=f2tff(vreg[i].y); vd[2]=f2tff(vreg[i].z); vd[3]=f2tff(vreg[i].w);
    }
    __syncthreads();

    const int nkt = q0 / 64 + 2;
    for (int kt2 = 0; kt2 < nkt; kt2++) {
        const int k0 = kt2 * 64;
        const int cb = kt2 & 1;
        const float* Ks = KsB + cb * KS_ELEMS;
        const float* Vs = VsB + cb * VS_ELEMS;
        const bool more = (kt2 + 1 < nkt);

        if (more) {
            const int kn = k0 + 64;
#pragma unroll
            for (int i = 0; i < 4; i++) {
                int row = kn + ldr + i * 16;
                kreg[i] = *(const float4*)&kp[(size_t)row * DH + ldc * 4];
                vreg[i] = *(const float4*)&vp[(size_t)row * DH + ldc * 4];
            }
        }

        float s[8][4];
#pragma unroll
        for (int nt = 0; nt < 8; nt++) { s[nt][0]=s[nt][1]=s[nt][2]=s[nt][3]=0.f; }
#pragma unroll
        for (int kt = 0; kt < 8; kt++)
#pragma unroll
            for (int nt = 0; nt < 8; nt++) {
                uint32_t b0 = __float_as_uint(Ks[(nt * 8 + g) * 68 + kt * 8 + t]);
                uint32_t b1 = __float_as_uint(Ks[(nt * 8 + g) * 68 + kt * 8 + t + 4]);
                mma_tf32(s[nt], qa[kt][0], qa[kt][1], qa[kt][2], qa[kt][3], b0, b1);
            }

        if (k0 + 63 > q0) {
#pragma unroll
            for (int nt = 0; nt < 8; nt++) {
                int col = k0 + nt * 8 + 2 * t;
                if (col > row0)     s[nt][0] = -1e30f;
                if (col + 1 > row0) s[nt][1] = -1e30f;
                if (col > row1)     s[nt][2] = -1e30f;
                if (col + 1 > row1) s[nt][3] = -1e30f;
            }
        }

        float mx0 = -1e30f, mx1 = -1e30f;
#pragma unroll
        for (int nt = 0; nt < 8; nt++) {
            mx0 = fmaxf(mx0, fmaxf(s[nt][0], s[nt][1]));
            mx1 = fmaxf(mx1, fmaxf(s[nt][2], s[nt][3]));
        }
        mx0 = fmaxf(mx0, __shfl_xor_sync(~0u, mx0, 1));
        mx0 = fmaxf(mx0, __shfl_xor_sync(~0u, mx0, 2));
        mx1 = fmaxf(mx1, __shfl_xor_sync(~0u, mx1, 1));
        mx1 = fmaxf(mx1, __shfl_xor_sync(~0u, mx1, 2));

        const float m0n = fmaxf(m0r, mx0), m1n = fmaxf(m1r, mx1);
        const float sc0 = __expf(m0r - m0n), sc1 = __expf(m1r - m1n);
        m0r = m0n; m1r = m1n;

        float r0 = 0.f, r1 = 0.f;
#pragma unroll
        for (int nt = 0; nt < 8; nt++) {
            s[nt][0] = __expf(s[nt][0] - m0n); s[nt][1] = __expf(s[nt][1] - m0n);
            s[nt][2] = __expf(s[nt][2] - m1n); s[nt][3] = __expf(s[nt][3] - m1n);
            r0 += s[nt][0] + s[nt][1]; r1 += s[nt][2] + s[nt][3];
        }
        r0 += __shfl_xor_sync(~0u, r0, 1); r0 += __shfl_xor_sync(~0u, r0, 2);
        r1 += __shfl_xor_sync(~0u, r1, 1); r1 += __shfl_xor_sync(~0u, r1, 2);
        l0 = l0 * sc0 + r0; l1 = l1 * sc1 + r1;

#pragma unroll
        for (int nt = 0; nt < 8; nt++) {
            o[nt][0] *= sc0; o[nt][1] *= sc0; o[nt][2] *= sc1; o[nt][3] *= sc1;
        }

        const int s0l = (lane & ~3) | (t >> 1), s1l = s0l + 2;
        const bool e = (t & 1);
#pragma unroll
        for (int kt = 0; kt < 8; kt++) {
            float v00 = __shfl_sync(~0u, s[kt][0], s0l), v01 = __shfl_sync(~0u, s[kt][1], s0l);
            float v10 = __shfl_sync(~0u, s[kt][2], s0l), v11 = __shfl_sync(~0u, s[kt][3], s0l);
            float w00 = __shfl_sync(~0u, s[kt][0], s1l), w01 = __shfl_sync(~0u, s[kt][1], s1l);
            float w10 = __shfl_sync(~0u, s[kt][2], s1l), w11 = __shfl_sync(~0u, s[kt][3], s1l);
            uint32_t pa0 = f2tf(e ? v01 : v00), pa1 = f2tf(e ? v11 : v10);
            uint32_t pa2 = f2tf(e ? w01 : w00), pa3 = f2tf(e ? w11 : w10);
#pragma unroll
            for (int nt = 0; nt < 8; nt++) {
                uint32_t b0 = __float_as_uint(Vs[(kt * 8 + t) * 72 + nt * 8 + g]);
                uint32_t b1 = __float_as_uint(Vs[(kt * 8 + t + 4) * 72 + nt * 8 + g]);
                mma_tf32(o[nt], pa0, pa1, pa2, pa3, b0, b1);
            }
        }

        if (more) {
            float* kd0 = KsB + (cb ^ 1) * KS_ELEMS;
            float* vd0 = VsB + (cb ^ 1) * VS_ELEMS;
#pragma unroll
            for (int i = 0; i < 4; i++) {
                int row = ldr + i * 16;
                float* kd = kd0 + row * 68 + ldc * 4;
                float* vd = vd0 + row * 72 + ldc * 4;
                kd[0]=f2tff(kreg[i].x); kd[1]=f2tff(kreg[i].y); kd[2]=f2tff(kreg[i].z); kd[3]=f2tff(kreg[i].w);
                vd[0]=f2tff(vreg[i].x); vd[1]=f2tff(vreg[i].y); vd[2]=f2tff(vreg[i].z); vd[3]=f2tff(vreg[i].w);
            }
            __syncthreads();
        }
    }

    const float inv0 = 1.f / l0, inv1 = 1.f / l1;
    float* or0 = g_o + ((size_t)(b * SEQ) + row0) * DM + h * DH;
    float* or1 = or0 + (size_t)8 * DM;
#pragma unroll
    for (int nt = 0; nt < 8; nt++) {
        int col = nt * 8 + 2 * t;
        float2 v0 = { o[nt][0] * inv0, o[nt][1] * inv0 };
        float2 v1 = { o[nt][2] * inv1, o[nt][3] * inv1 };
        *(float2*)&or0[col] = v0;
        *(float2*)&or1[col] = v1;
    }
}

// ---------------------------------------------------------------------------
// Output projection: 128x128 tile, 8 warps of 32x64, reg prefetch.
// ---------------------------------------------------------------------------
__global__ __launch_bounds__(256) void oproj_kernel(
    const float* __restrict__ Ow, const float* __restrict__ Ob,
    float* __restrict__ out)
{
    const int m0 = blockIdx.x * 128;
    const int n0 = blockIdx.y * 128;

    __shared__ float As[128][36];
    __shared__ float Bs[32][136];

    const int tid  = threadIdx.x;
    const int lane = tid & 31;
    const int w    = tid >> 5;
    const int wm   = w >> 1;
    const int wn   = w & 1;
    const int g    = lane >> 2;
    const int t    = lane & 3;

    float c[2][8][4];
#pragma unroll
    for (int mt = 0; mt < 2; mt++)
#pragma unroll
        for (int nt = 0; nt < 8; nt++)
#pragma unroll
            for (int i = 0; i < 4; i++) c[mt][nt][i] = 0.f;

    const int arow = tid >> 3, ac4 = tid & 7;
    const int brow = tid >> 5, bc4 = tid & 31;

    float4 areg[4], breg[4];
#pragma unroll
    for (int i = 0; i < 4; i++) {
        areg[i] = *(const float4*)&g_o[(size_t)(m0 + arow + i * 32) * DM + ac4 * 4];
        breg[i] = *(const float4*)&Ow[(size_t)(brow + i * 8) * DM + n0 + bc4 * 4];
    }

    for (int k0 = 0; k0 < DM; k0 += 32) {
#pragma unroll
        for (int i = 0; i < 4; i++) {
            int row = arow + i * 32;
            As[row][ac4 * 4 + 0] = f2tff(areg[i].x);
            As[row][ac4 * 4 + 1] = f2tff(areg[i].y);
            As[row][ac4 * 4 + 2] = f2tff(areg[i].z);
            As[row][ac4 * 4 + 3] = f2tff(areg[i].w);
            int rb = brow + i * 8;
            Bs[rb][bc4 * 4 + 0] = f2tff(breg[i].x);
            Bs[rb][bc4 * 4 + 1] = f2tff(breg[i].y);
            Bs[rb][bc4 * 4 + 2] = f2tff(breg[i].z);
            Bs[rb][bc4 * 4 + 3] = f2tff(breg[i].w);
        }
        __syncthreads();

        if (k0 + 32 < DM) {
            const int kn = k0 + 32;
#pragma unroll
            for (int i = 0; i < 4; i++) {
                areg[i] = *(const float4*)&g_o[(size_t)(m0 + arow + i * 32) * DM + kn + ac4 * 4];
                breg[i] = *(const float4*)&Ow[(size_t)(kn + brow + i * 8) * DM + n0 + bc4 * 4];
            }
        }

#pragma unroll
        for (int ks = 0; ks < 4; ks++) {
            uint32_t a[2][4], bb[8][2];
#pragma unroll
            for (int mt = 0; mt < 2; mt++) {
                int r0 = wm * 32 + mt * 16 + g;
                a[mt][0] = __float_as_uint(As[r0][ks * 8 + t]);
                a[mt][1] = __float_as_uint(As[r0 + 8][ks * 8 + t]);
                a[mt][2] = __float_as_uint(As[r0][ks * 8 + t + 4]);
                a[mt][3] = __float_as_uint(As[r0 + 8][ks * 8 + t + 4]);
            }
#pragma unroll
            for (int nt = 0; nt < 8; nt++) {
                int col = wn * 64 + nt * 8 + g;
                bb[nt][0] = __float_as_uint(Bs[ks * 8 + t][col]);
                bb[nt][1] = __float_as_uint(Bs[ks * 8 + t + 4][col]);
            }
#pragma unroll
            for (int mt = 0; mt < 2; mt++)
#pragma unroll
                for (int nt = 0; nt < 8; nt++)
                    mma_tf32(c[mt][nt], a[mt][0], a[mt][1], a[mt][2], a[mt][3],
                             bb[nt][0], bb[nt][1]);
        }
        __syncthreads();
    }

#pragma unroll
    for (int mt = 0; mt < 2; mt++) {
        int m = m0 + wm * 32 + mt * 16 + g;
        float* dst = out + (size_t)m * DM + n0 + wn * 64;
        const float* bi = Ob + n0 + wn * 64;
#pragma unroll
        for (int nt = 0; nt < 8; nt++) {
            int d = nt * 8 + 2 * t;
            float bx = bi[d], by = bi[d + 1];
            float2 v0 = { c[mt][nt][0] + bx, c[mt][nt][1] + by };
            float2 v1 = { c[mt][nt][2] + bx, c[mt][nt][3] + by };
            *(float2*)&dst[d]          = v0;
            *(float2*)&dst[8 * DM + d] = v1;
        }
    }
}

extern "C" void kernel_launch(void* const* d_in, const int* in_sizes, int n_in,
                              void* d_out, int out_size)
{
    const float* x  = (const float*)d_in[0];
    const float* Qw = (const float*)d_in[1];
    const float* Qb = (const float*)d_in[2];
    const float* Kw = (const float*)d_in[3];
    const float* Kb = (const float*)d_in[4];
    const float* Vw = (const float*)d_in[5];
    const float* Vb = (const float*)d_in[6];
    const float* Ow = (const float*)d_in[7];
    const float* Ob = (const float*)d_in[8];
    float* out = (float*)d_out;

    static int s_init = 0;
    if (!s_init) {
        cudaFuncSetAttribute(attn_kernel,
            cudaFuncAttributeMaxDynamicSharedMemorySize, ATTN_SMEM);
        s_init = 1;
    }

    qkv_kernel<<<dim3(MROWS / 128, NH / 2, 3), 256>>>(x, Qw, Qb, Kw, Kb, Vw, Vb);
    attn_kernel<<<dim3(SEQ / 128, BATCH * NH), 256, ATTN_SMEM>>>();
    oproj_kernel<<<dim3(MROWS / 128, DM / 128), 256>>>(Ow, Ob, out);
}

// round 8
// speedup vs baseline: 1.8484x; 1.0021x over previous
#include <cuda_runtime.h>
#include <cstdint>

#define BATCH 4
#define SEQ   2048
#define NH    16
#define DH    64
#define DM    1024
#define MROWS (BATCH*SEQ)

__device__ float g_q[(size_t)BATCH*NH*SEQ*DH];
__device__ float g_k[(size_t)BATCH*NH*SEQ*DH];
__device__ float g_v[(size_t)BATCH*NH*SEQ*DH];
__device__ float g_o[(size_t)MROWS*DM];

__device__ __forceinline__ uint32_t f2tf(float x) {
    uint32_t u;
    asm("cvt.rna.tf32.f32 %0, %1;" : "=r"(u) : "f"(x));
    return u;
}
__device__ __forceinline__ float f2tff(float x) { return __uint_as_float(f2tf(x)); }

__device__ __forceinline__ void mma_tf32(float* c,
    uint32_t a0, uint32_t a1, uint32_t a2, uint32_t a3,
    uint32_t b0, uint32_t b1)
{
    asm volatile(
        "mma.sync.aligned.m16n8k8.row.col.f32.tf32.tf32.f32 "
        "{%0,%1,%2,%3}, {%4,%5,%6,%7}, {%8,%9}, {%0,%1,%2,%3};"
        : "+f"(c[0]), "+f"(c[1]), "+f"(c[2]), "+f"(c[3])
        : "r"(a0), "r"(a1), "r"(a2), "r"(a3), "r"(b0), "r"(b1));
}

// Stage layout: As 128x36 floats then Bs 32x136 floats
#define GA_STRIDE 36
#define GB_STRIDE 136
#define AS_FLOATS (128 * GA_STRIDE)          // 4608
#define STAGE_FLOATS (AS_FLOATS + 32 * GB_STRIDE)  // 4608 + 4352 = 8960
#define GEMM_SMEM (2 * STAGE_FLOATS * 4)     // 71680 bytes

// ---------------------------------------------------------------------------
// QKV projection: 128x128 tile (2 heads), double-buffered smem, 1 sync/iter.
// ---------------------------------------------------------------------------
__global__ __launch_bounds__(256) void qkv_kernel(
    const float* __restrict__ X,
    const float* __restrict__ Qw, const float* __restrict__ Qb,
    const float* __restrict__ Kw, const float* __restrict__ Kb,
    const float* __restrict__ Vw, const float* __restrict__ Vb)
{
    extern __shared__ float sm[];

    const int m0    = blockIdx.x * 128;
    const int hp    = blockIdx.y;
    const int which = blockIdx.z;

    const float* W    = (which == 0 ? Qw : which == 1 ? Kw : Vw);
    const float* bias = (which == 0 ? Qb : which == 1 ? Kb : Vb);
    float* Out        = (which == 0 ? g_q : which == 1 ? g_k : g_v);

    const int tid  = threadIdx.x;
    const int lane = tid & 31;
    const int w    = tid >> 5;
    const int wm   = w >> 1;
    const int wn   = w & 1;
    const int g    = lane >> 2;
    const int t    = lane & 3;

    float c[2][8][4];
#pragma unroll
    for (int mt = 0; mt < 2; mt++)
#pragma unroll
        for (int nt = 0; nt < 8; nt++)
#pragma unroll
            for (int i = 0; i < 4; i++) c[mt][nt][i] = 0.f;

    const int arow = tid >> 3, ac4 = tid & 7;
    const int brow = tid >> 5, bc4 = tid & 31;
    const int bh   = 2 * hp + (bc4 >> 4);
    const int bd   = (bc4 & 15) * 4;

    float4 areg[4], breg[4];
#pragma unroll
    for (int i = 0; i < 4; i++) {
        areg[i] = *(const float4*)&X[(size_t)(m0 + arow + i * 32) * DM + ac4 * 4];
        breg[i] = *(const float4*)&W[((size_t)bh * DM + brow + i * 8) * DH + bd];
    }
    // stage 0 STS
    {
        float* As = sm;
        float* Bs = sm + AS_FLOATS;
#pragma unroll
        for (int i = 0; i < 4; i++) {
            float* ad = As + (arow + i * 32) * GA_STRIDE + ac4 * 4;
            ad[0]=f2tff(areg[i].x); ad[1]=f2tff(areg[i].y); ad[2]=f2tff(areg[i].z); ad[3]=f2tff(areg[i].w);
            float* bdp = Bs + (brow + i * 8) * GB_STRIDE + bc4 * 4;
            bdp[0]=f2tff(breg[i].x); bdp[1]=f2tff(breg[i].y); bdp[2]=f2tff(breg[i].z); bdp[3]=f2tff(breg[i].w);
        }
    }

    for (int it = 0; it < 32; it++) {
        __syncthreads();
        const bool more = (it + 1 < 32);
        if (more) {
            const int kn = (it + 1) * 32;
#pragma unroll
            for (int i = 0; i < 4; i++) {
                areg[i] = *(const float4*)&X[(size_t)(m0 + arow + i * 32) * DM + kn + ac4 * 4];
                breg[i] = *(const float4*)&W[((size_t)bh * DM + kn + brow + i * 8) * DH + bd];
            }
        }

        const float* As = sm + (it & 1) * STAGE_FLOATS;
        const float* Bs = As + AS_FLOATS;
#pragma unroll
        for (int ks = 0; ks < 4; ks++) {
            uint32_t a[2][4], bb[8][2];
#pragma unroll
            for (int mt = 0; mt < 2; mt++) {
                const float* ar = As + (wm * 32 + mt * 16 + g) * GA_STRIDE + ks * 8;
                a[mt][0] = __float_as_uint(ar[t]);
                a[mt][1] = __float_as_uint(ar[8 * GA_STRIDE + t]);
                a[mt][2] = __float_as_uint(ar[t + 4]);
                a[mt][3] = __float_as_uint(ar[8 * GA_STRIDE + t + 4]);
            }
#pragma unroll
            for (int nt = 0; nt < 8; nt++) {
                const float* br = Bs + (ks * 8 + t) * GB_STRIDE + wn * 64 + nt * 8 + g;
                bb[nt][0] = __float_as_uint(br[0]);
                bb[nt][1] = __float_as_uint(br[4 * GB_STRIDE]);
            }
#pragma unroll
            for (int mt = 0; mt < 2; mt++)
#pragma unroll
                for (int nt = 0; nt < 8; nt++)
                    mma_tf32(c[mt][nt], a[mt][0], a[mt][1], a[mt][2], a[mt][3],
                             bb[nt][0], bb[nt][1]);
        }

        if (more) {
            float* As2 = sm + ((it + 1) & 1) * STAGE_FLOATS;
            float* Bs2 = As2 + AS_FLOATS;
#pragma unroll
            for (int i = 0; i < 4; i++) {
                float* ad = As2 + (arow + i * 32) * GA_STRIDE + ac4 * 4;
                ad[0]=f2tff(areg[i].x); ad[1]=f2tff(areg[i].y); ad[2]=f2tff(areg[i].z); ad[3]=f2tff(areg[i].w);
                float* bdp = Bs2 + (brow + i * 8) * GB_STRIDE + bc4 * 4;
                bdp[0]=f2tff(breg[i].x); bdp[1]=f2tff(breg[i].y); bdp[2]=f2tff(breg[i].z); bdp[3]=f2tff(breg[i].w);
            }
        }
    }

    const int h = 2 * hp + wn;
    const float* bi = bias + h * DH;
#pragma unroll
    for (int mt = 0; mt < 2; mt++) {
        int m = m0 + wm * 32 + mt * 16 + g;
        int b_ = m >> 11, p = m & 2047;
        float* dst = Out + (((size_t)(b_ * NH + h)) * SEQ + p) * DH;
#pragma unroll
        for (int nt = 0; nt < 8; nt++) {
            int d = nt * 8 + 2 * t;
            float bx = bi[d], by = bi[d + 1];
            float2 v0 = { c[mt][nt][0] + bx, c[mt][nt][1] + by };
            float2 v1 = { c[mt][nt][2] + bx, c[mt][nt][3] + by };
            *(float2*)&dst[d]          = v0;
            *(float2*)&dst[8 * DH + d] = v1;
        }
    }
}

// ---------------------------------------------------------------------------
// Causal flash attention (unchanged from R7: double-buffered, 1 sync/tile)
// ---------------------------------------------------------------------------
#define KS_ELEMS (64 * 68)
#define VS_ELEMS (64 * 72)
#define ATTN_SMEM ((2 * KS_ELEMS + 2 * VS_ELEMS) * 4)

__global__ __launch_bounds__(256) void attn_kernel()
{
    extern __shared__ float sm[];
    float* KsB = sm;
    float* VsB = sm + 2 * KS_ELEMS;

    const int qt = (SEQ / 128 - 1) - blockIdx.x;
    const int bh = blockIdx.y;
    const int q0 = qt * 128;
    const int b  = bh / NH, h = bh % NH;

    const float* qp = g_q + (size_t)bh * SEQ * DH;
    const float* kp = g_k + (size_t)bh * SEQ * DH;
    const float* vp = g_v + (size_t)bh * SEQ * DH;

    const int tid  = threadIdx.x;
    const int lane = tid & 31;
    const int w    = tid >> 5;
    const int g    = lane >> 2;
    const int t    = lane & 3;

    uint32_t qa[8][4];
    {
        const float* qr0 = qp + (size_t)(q0 + w * 16 + g) * DH;
        const float* qr1 = qr0 + 8 * DH;
#pragma unroll
        for (int kt = 0; kt < 8; kt++) {
            qa[kt][0] = f2tf(qr0[kt * 8 + t] * 0.125f);
            qa[kt][1] = f2tf(qr1[kt * 8 + t] * 0.125f);
            qa[kt][2] = f2tf(qr0[kt * 8 + t + 4] * 0.125f);
            qa[kt][3] = f2tf(qr1[kt * 8 + t + 4] * 0.125f);
        }
    }

    float o[8][4];
#pragma unroll
    for (int nt = 0; nt < 8; nt++) { o[nt][0]=o[nt][1]=o[nt][2]=o[nt][3]=0.f; }
    float m0r = -1e30f, m1r = -1e30f, l0 = 0.f, l1 = 0.f;
    const int row0 = q0 + w * 16 + g, row1 = row0 + 8;

    const int ldr = tid >> 4, ldc = tid & 15;

    float4 kreg[4], vreg[4];
#pragma unroll
    for (int i = 0; i < 4; i++) {
        int row = ldr + i * 16;
        kreg[i] = *(const float4*)&kp[(size_t)row * DH + ldc * 4];
        vreg[i] = *(const float4*)&vp[(size_t)row * DH + ldc * 4];
    }
#pragma unroll
    for (int i = 0; i < 4; i++) {
        int row = ldr + i * 16;
        float* kd = KsB + row * 68 + ldc * 4;
        float* vd = VsB + row * 72 + ldc * 4;
        kd[0]=f2tff(kreg[i].x); kd[1]=f2tff(kreg[i].y); kd[2]=f2tff(kreg[i].z); kd[3]=f2tff(kreg[i].w);
        vd[0]=f2tff(vreg[i].x); vd[1]=f2tff(vreg[i].y); vd[2]=f2tff(vreg[i].z); vd[3]=f2tff(vreg[i].w);
    }
    __syncthreads();

    const int nkt = q0 / 64 + 2;
    for (int kt2 = 0; kt2 < nkt; kt2++) {
        const int k0 = kt2 * 64;
        const int cb = kt2 & 1;
        const float* Ks = KsB + cb * KS_ELEMS;
        const float* Vs = VsB + cb * VS_ELEMS;
        const bool more = (kt2 + 1 < nkt);

        if (more) {
            const int kn = k0 + 64;
#pragma unroll
            for (int i = 0; i < 4; i++) {
                int row = kn + ldr + i * 16;
                kreg[i] = *(const float4*)&kp[(size_t)row * DH + ldc * 4];
                vreg[i] = *(const float4*)&vp[(size_t)row * DH + ldc * 4];
            }
        }

        float s[8][4];
#pragma unroll
        for (int nt = 0; nt < 8; nt++) { s[nt][0]=s[nt][1]=s[nt][2]=s[nt][3]=0.f; }
#pragma unroll
        for (int kt = 0; kt < 8; kt++)
#pragma unroll
            for (int nt = 0; nt < 8; nt++) {
                uint32_t b0 = __float_as_uint(Ks[(nt * 8 + g) * 68 + kt * 8 + t]);
                uint32_t b1 = __float_as_uint(Ks[(nt * 8 + g) * 68 + kt * 8 + t + 4]);
                mma_tf32(s[nt], qa[kt][0], qa[kt][1], qa[kt][2], qa[kt][3], b0, b1);
            }

        if (k0 + 63 > q0) {
#pragma unroll
            for (int nt = 0; nt < 8; nt++) {
                int col = k0 + nt * 8 + 2 * t;
                if (col > row0)     s[nt][0] = -1e30f;
                if (col + 1 > row0) s[nt][1] = -1e30f;
                if (col > row1)     s[nt][2] = -1e30f;
                if (col + 1 > row1) s[nt][3] = -1e30f;
            }
        }

        float mx0 = -1e30f, mx1 = -1e30f;
#pragma unroll
        for (int nt = 0; nt < 8; nt++) {
            mx0 = fmaxf(mx0, fmaxf(s[nt][0], s[nt][1]));
            mx1 = fmaxf(mx1, fmaxf(s[nt][2], s[nt][3]));
        }
        mx0 = fmaxf(mx0, __shfl_xor_sync(~0u, mx0, 1));
        mx0 = fmaxf(mx0, __shfl_xor_sync(~0u, mx0, 2));
        mx1 = fmaxf(mx1, __shfl_xor_sync(~0u, mx1, 1));
        mx1 = fmaxf(mx1, __shfl_xor_sync(~0u, mx1, 2));

        const float m0n = fmaxf(m0r, mx0), m1n = fmaxf(m1r, mx1);
        const float sc0 = __expf(m0r - m0n), sc1 = __expf(m1r - m1n);
        m0r = m0n; m1r = m1n;

        float r0 = 0.f, r1 = 0.f;
#pragma unroll
        for (int nt = 0; nt < 8; nt++) {
            s[nt][0] = __expf(s[nt][0] - m0n); s[nt][1] = __expf(s[nt][1] - m0n);
            s[nt][2] = __expf(s[nt][2] - m1n); s[nt][3] = __expf(s[nt][3] - m1n);
            r0 += s[nt][0] + s[nt][1]; r1 += s[nt][2] + s[nt][3];
        }
        r0 += __shfl_xor_sync(~0u, r0, 1); r0 += __shfl_xor_sync(~0u, r0, 2);
        r1 += __shfl_xor_sync(~0u, r1, 1); r1 += __shfl_xor_sync(~0u, r1, 2);
        l0 = l0 * sc0 + r0; l1 = l1 * sc1 + r1;

#pragma unroll
        for (int nt = 0; nt < 8; nt++) {
            o[nt][0] *= sc0; o[nt][1] *= sc0; o[nt][2] *= sc1; o[nt][3] *= sc1;
        }

        const int s0l = (lane & ~3) | (t >> 1), s1l = s0l + 2;
        const bool e = (t & 1);
#pragma unroll
        for (int kt = 0; kt < 8; kt++) {
            float v00 = __shfl_sync(~0u, s[kt][0], s0l), v01 = __shfl_sync(~0u, s[kt][1], s0l);
            float v10 = __shfl_sync(~0u, s[kt][2], s0l), v11 = __shfl_sync(~0u, s[kt][3], s0l);
            float w00 = __shfl_sync(~0u, s[kt][0], s1l), w01 = __shfl_sync(~0u, s[kt][1], s1l);
            float w10 = __shfl_sync(~0u, s[kt][2], s1l), w11 = __shfl_sync(~0u, s[kt][3], s1l);
            uint32_t pa0 = f2tf(e ? v01 : v00), pa1 = f2tf(e ? v11 : v10);
            uint32_t pa2 = f2tf(e ? w01 : w00), pa3 = f2tf(e ? w11 : w10);
#pragma unroll
            for (int nt = 0; nt < 8; nt++) {
                uint32_t b0 = __float_as_uint(Vs[(kt * 8 + t) * 72 + nt * 8 + g]);
                uint32_t b1 = __float_as_uint(Vs[(kt * 8 + t + 4) * 72 + nt * 8 + g]);
                mma_tf32(o[nt], pa0, pa1, pa2, pa3, b0, b1);
            }
        }

        if (more) {
            float* kd0 = KsB + (cb ^ 1) * KS_ELEMS;
            float* vd0 = VsB + (cb ^ 1) * VS_ELEMS;
#pragma unroll
            for (int i = 0; i < 4; i++) {
                int row = ldr + i * 16;
                float* kd = kd0 + row * 68 + ldc * 4;
                float* vd = vd0 + row * 72 + ldc * 4;
                kd[0]=f2tff(kreg[i].x); kd[1]=f2tff(kreg[i].y); kd[2]=f2tff(kreg[i].z); kd[3]=f2tff(kreg[i].w);
                vd[0]=f2tff(vreg[i].x); vd[1]=f2tff(vreg[i].y); vd[2]=f2tff(vreg[i].z); vd[3]=f2tff(vreg[i].w);
            }
            __syncthreads();
        }
    }

    const float inv0 = 1.f / l0, inv1 = 1.f / l1;
    float* or0 = g_o + ((size_t)(b * SEQ) + row0) * DM + h * DH;
    float* or1 = or0 + (size_t)8 * DM;
#pragma unroll
    for (int nt = 0; nt < 8; nt++) {
        int col = nt * 8 + 2 * t;
        float2 v0 = { o[nt][0] * inv0, o[nt][1] * inv0 };
        float2 v1 = { o[nt][2] * inv1, o[nt][3] * inv1 };
        *(float2*)&or0[col] = v0;
        *(float2*)&or1[col] = v1;
    }
}

// ---------------------------------------------------------------------------
// Output projection: 128x128 tile, double-buffered smem, 1 sync/iter.
// ---------------------------------------------------------------------------
__global__ __launch_bounds__(256) void oproj_kernel(
    const float* __restrict__ Ow, const float* __restrict__ Ob,
    float* __restrict__ out)
{
    extern __shared__ float sm[];

    const int m0 = blockIdx.x * 128;
    const int n0 = blockIdx.y * 128;

    const int tid  = threadIdx.x;
    const int lane = tid & 31;
    const int w    = tid >> 5;
    const int wm   = w >> 1;
    const int wn   = w & 1;
    const int g    = lane >> 2;
    const int t    = lane & 3;

    float c[2][8][4];
#pragma unroll
    for (int mt = 0; mt < 2; mt++)
#pragma unroll
        for (int nt = 0; nt < 8; nt++)
#pragma unroll
            for (int i = 0; i < 4; i++) c[mt][nt][i] = 0.f;

    const int arow = tid >> 3, ac4 = tid & 7;
    const int brow = tid >> 5, bc4 = tid & 31;

    float4 areg[4], breg[4];
#pragma unroll
    for (int i = 0; i < 4; i++) {
        areg[i] = *(const float4*)&g_o[(size_t)(m0 + arow + i * 32) * DM + ac4 * 4];
        breg[i] = *(const float4*)&Ow[(size_t)(brow + i * 8) * DM + n0 + bc4 * 4];
    }
    {
        float* As = sm;
        float* Bs = sm + AS_FLOATS;
#pragma unroll
        for (int i = 0; i < 4; i++) {
            float* ad = As + (arow + i * 32) * GA_STRIDE + ac4 * 4;
            ad[0]=f2tff(areg[i].x); ad[1]=f2tff(areg[i].y); ad[2]=f2tff(areg[i].z); ad[3]=f2tff(areg[i].w);
            float* bdp = Bs + (brow + i * 8) * GB_STRIDE + bc4 * 4;
            bdp[0]=f2tff(breg[i].x); bdp[1]=f2tff(breg[i].y); bdp[2]=f2tff(breg[i].z); bdp[3]=f2tff(breg[i].w);
        }
    }

    for (int it = 0; it < 32; it++) {
        __syncthreads();
        const bool more = (it + 1 < 32);
        if (more) {
            const int kn = (it + 1) * 32;
#pragma unroll
            for (int i = 0; i < 4; i++) {
                areg[i] = *(const float4*)&g_o[(size_t)(m0 + arow + i * 32) * DM + kn + ac4 * 4];
                breg[i] = *(const float4*)&Ow[(size_t)(kn + brow + i * 8) * DM + n0 + bc4 * 4];
            }
        }

        const float* As = sm + (it & 1) * STAGE_FLOATS;
        const float* Bs = As + AS_FLOATS;
#pragma unroll
        for (int ks = 0; ks < 4; ks++) {
            uint32_t a[2][4], bb[8][2];
#pragma unroll
            for (int mt = 0; mt < 2; mt++) {
                const float* ar = As + (wm * 32 + mt * 16 + g) * GA_STRIDE + ks * 8;
                a[mt][0] = __float_as_uint(ar[t]);
                a[mt][1] = __float_as_uint(ar[8 * GA_STRIDE + t]);
                a[mt][2] = __float_as_uint(ar[t + 4]);
                a[mt][3] = __float_as_uint(ar[8 * GA_STRIDE + t + 4]);
            }
#pragma unroll
            for (int nt = 0; nt < 8; nt++) {
                const float* br = Bs + (ks * 8 + t) * GB_STRIDE + wn * 64 + nt * 8 + g;
                bb[nt][0] = __float_as_uint(br[0]);
                bb[nt][1] = __float_as_uint(br[4 * GB_STRIDE]);
            }
#pragma unroll
            for (int mt = 0; mt < 2; mt++)
#pragma unroll
                for (int nt = 0; nt < 8; nt++)
                    mma_tf32(c[mt][nt], a[mt][0], a[mt][1], a[mt][2], a[mt][3],
                             bb[nt][0], bb[nt][1]);
        }

        if (more) {
            float* As2 = sm + ((it + 1) & 1) * STAGE_FLOATS;
            float* Bs2 = As2 + AS_FLOATS;
#pragma unroll
            for (int i = 0; i < 4; i++) {
                float* ad = As2 + (arow + i * 32) * GA_STRIDE + ac4 * 4;
                ad[0]=f2tff(areg[i].x); ad[1]=f2tff(areg[i].y); ad[2]=f2tff(areg[i].z); ad[3]=f2tff(areg[i].w);
                float* bdp = Bs2 + (brow + i * 8) * GB_STRIDE + bc4 * 4;
                bdp[0]=f2tff(breg[i].x); bdp[1]=f2tff(breg[i].y); bdp[2]=f2tff(breg[i].z); bdp[3]=f2tff(breg[i].w);
            }
        }
    }

#pragma unroll
    for (int mt = 0; mt < 2; mt++) {
        int m = m0 + wm * 32 + mt * 16 + g;
        float* dst = out + (size_t)m * DM + n0 + wn * 64;
        const float* bi = Ob + n0 + wn * 64;
#pragma unroll
        for (int nt = 0; nt < 8; nt++) {
            int d = nt * 8 + 2 * t;
            float bx = bi[d], by = bi[d + 1];
            float2 v0 = { c[mt][nt][0] + bx, c[mt][nt][1] + by };
            float2 v1 = { c[mt][nt][2] + bx, c[mt][nt][3] + by };
            *(float2*)&dst[d]          = v0;
            *(float2*)&dst[8 * DM + d] = v1;
        }
    }
}

extern "C" void kernel_launch(void* const* d_in, const int* in_sizes, int n_in,
                              void* d_out, int out_size)
{
    const float* x  = (const float*)d_in[0];
    const float* Qw = (const float*)d_in[1];
    const float* Qb = (const float*)d_in[2];
    const float* Kw = (const float*)d_in[3];
    const float* Kb = (const float*)d_in[4];
    const float* Vw = (const float*)d_in[5];
    const float* Vb = (const float*)d_in[6];
    const float* Ow = (const float*)d_in[7];
    const float* Ob = (const float*)d_in[8];
    float* out = (float*)d_out;

    static int s_init = 0;
    if (!s_init) {
        cudaFuncSetAttribute(attn_kernel,
            cudaFuncAttributeMaxDynamicSharedMemorySize, ATTN_SMEM);
        cudaFuncSetAttribute(qkv_kernel,
            cudaFuncAttributeMaxDynamicSharedMemorySize, GEMM_SMEM);
        cudaFuncSetAttribute(oproj_kernel,
            cudaFuncAttributeMaxDynamicSharedMemorySize, GEMM_SMEM);
        s_init = 1;
    }

    qkv_kernel<<<dim3(MROWS / 128, NH / 2, 3), 256, GEMM_SMEM>>>(x, Qw, Qb, Kw, Kb, Vw, Vb);
    attn_kernel<<<dim3(SEQ / 128, BATCH * NH), 256, ATTN_SMEM>>>();
    oproj_kernel<<<dim3(MROWS / 128, DM / 128), 256, GEMM_SMEM>>>(Ow, Ob, out);
}